// round 13
// baseline (speedup 1.0000x reference)
#include <cuda_runtime.h>
#include <cstdint>
#include <cstddef>

// Problem constants
#define BQ    8
#define CIN   64
#define TLEN  1024
#define FF    256
#define COUT  64
#define GG    32
#define UU    8

// Tiling
#define O_PER_CTA 32
#define TILE_T    128
#define ICHUNK    4
#define NCHUNK    (CIN / ICHUNK)     // 16

// SMEM layout (floats)
#define WS_FLOATS   (4 * CIN * 64)           // ws[up][i][o*2+j] : 16384 (64KB)
#define XS_TSTRIDE  10                        // 8 data + 2 pad
#define XS_ISTRIDE  (TILE_T * XS_TSTRIDE)     // 1280
#define XS_BUF      (ICHUNK * XS_ISTRIDE)     // 5120
#define XS_FLOATS   (2 * XS_BUF)              // 10240 (40KB double-buffered)
#define BS_FLOATS   256                       // bias slice [32o][8u]
#define SMEM_FLOATS (WS_FLOATS + XS_FLOATS + BS_FLOATS)
#define SMEM_BYTES  (SMEM_FLOATS * 4)         // 107520 B -> 2 CTAs/SM

typedef unsigned long long ull;

__device__ __forceinline__ void fma2(ull& d, ull a, ull b) {
    asm("fma.rn.f32x2 %0, %1, %2, %0;" : "+l"(d) : "l"(a), "l"(b));
}
__device__ __forceinline__ float2 unpack2(ull v) {
    unsigned lo, hi;
    asm("mov.b64 {%0, %1}, %2;" : "=r"(lo), "=r"(hi) : "l"(v));
    return make_float2(__uint_as_float(lo), __uint_as_float(hi));
}
__device__ __forceinline__ void cp_async8(uint32_t dst, const void* src) {
    asm volatile("cp.async.ca.shared.global [%0], [%1], 8;\n" :: "r"(dst), "l"(src));
}
__device__ __forceinline__ void cp_commit() {
    asm volatile("cp.async.commit_group;\n" ::: "memory");
}
template <int N>
__device__ __forceinline__ void cp_wait() {
    asm volatile("cp.async.wait_group %0;\n" :: "n"(N) : "memory");
}

__global__ void __launch_bounds__(512, 2)
grouped_linear_cf_kernel(const float* __restrict__ x,
                         const float* __restrict__ w,
                         const float* __restrict__ bias,
                         float* __restrict__ y)
{
    extern __shared__ float smem[];
    float* ws = smem;                          // [up][i][o*2+j]
    float* xs = smem + WS_FLOATS;              // [buf][i_local][t][u] stride-10
    float* bs = smem + WS_FLOATS + XS_FLOATS;  // bias [o][u]

    const int g   = blockIdx.x;
    const int b   = blockIdx.y;
    const int oh  = blockIdx.z & 1;            // o-half
    const int tz  = blockIdx.z >> 1;           // t-range (8 x 128)
    const int tid = threadIdx.x;

    const int lane = tid & 31;
    const int warp = tid >> 5;
    const int up   = warp & 3;                 // u-pair
    const int og   = warp >> 2;                // o-octet (0..3)
    const int u0   = up * 2;
    const int t0   = tz * TILE_T;

    const float* xg = x + (size_t)b * CIN * TLEN * FF + (size_t)g * UU;

    // ---- prologue: cp.async chunk 0 into buf 0 (4i x 128t x 4seg = 2048) ----
    {
#pragma unroll
        for (int kk = 0; kk < 4; ++kk) {
            int idx = tid + kk * 512;
            int il  = idx >> 9;
            int rem = idx & 511;
            int t   = rem >> 2;
            int seg = rem & 3;
            const float* src = xg + (size_t)il * (TLEN * FF)
                                  + (size_t)(t0 + t) * FF + seg * 2;
            uint32_t dst = (uint32_t)__cvta_generic_to_shared(
                xs + il * XS_ISTRIDE + t * XS_TSTRIDE + seg * 2);
            cp_async8(dst, src);
        }
        cp_commit();
    }

    // ---- weights -> SMEM (once): ws[up][i][o*2+j] = w[g][2up+j][i][oh*32+o] ----
    {
        const float* wgl = w + (size_t)g * (UU * CIN * COUT) + oh * O_PER_CTA;
#pragma unroll
        for (int kk = 0; kk < 32; ++kk) {
            int idx = tid + kk * 512;          // 16384: 8u x 64i x 32o
            int uu  = idx >> 11;
            int i   = (idx >> 5) & 63;
            int o   = idx & 31;
            ws[(uu >> 1) * (CIN * 64) + i * 64 + o * 2 + (uu & 1)] =
                wgl[((size_t)uu * CIN + i) * COUT + o];
        }
    }
    // ---- bias slice -> SMEM: bs[o*8+u] ----
    if (tid < 256) {
        int o = tid >> 3, u = tid & 7;
        bs[tid] = bias[(size_t)(oh * O_PER_CTA + o) * FF + g * UU + u];
    }

    ull acc[4][8];
#pragma unroll
    for (int k = 0; k < 4; ++k)
#pragma unroll
        for (int oo = 0; oo < 8; ++oo) acc[k][oo] = 0ull;

    for (int ic = 0; ic < NCHUNK; ++ic) {
        if (ic + 1 < NCHUNK) {
            float* dstb = xs + ((ic + 1) & 1) * XS_BUF;
            const int ibase = (ic + 1) * ICHUNK;
#pragma unroll
            for (int kk = 0; kk < 4; ++kk) {
                int idx = tid + kk * 512;
                int il  = idx >> 9;
                int rem = idx & 511;
                int t   = rem >> 2;
                int seg = rem & 3;
                const float* src = xg + (size_t)(ibase + il) * (TLEN * FF)
                                      + (size_t)(t0 + t) * FF + seg * 2;
                uint32_t dst = (uint32_t)__cvta_generic_to_shared(
                    dstb + il * XS_ISTRIDE + t * XS_TSTRIDE + seg * 2);
                cp_async8(dst, src);
            }
            cp_commit();
            cp_wait<1>();
        } else {
            cp_wait<0>();
        }
        __syncthreads();

        const float* xb = xs + (ic & 1) * XS_BUF + lane * XS_TSTRIDE + u0;
        const float* wb = ws + up * (CIN * 64) + og * 16 + ic * ICHUNK * 64;

#pragma unroll
        for (int il = 0; il < ICHUNK; ++il) {
            // x u-pairs at t = lane, lane+32, lane+64, lane+96 (conflict-free LDS.64)
            const float* xr = xb + il * XS_ISTRIDE;
            ull xv0 = *reinterpret_cast<const ull*>(xr);
            ull xv1 = *reinterpret_cast<const ull*>(xr + 32 * XS_TSTRIDE);
            ull xv2 = *reinterpret_cast<const ull*>(xr + 64 * XS_TSTRIDE);
            ull xv3 = *reinterpret_cast<const ull*>(xr + 96 * XS_TSTRIDE);

            // 8 o's worth of w u-pairs: 4 x LDS.128, all lanes same address (broadcast)
            const float* wr = wb + il * 64;
            ulonglong2 wq0 = *reinterpret_cast<const ulonglong2*>(wr);
            ulonglong2 wq1 = *reinterpret_cast<const ulonglong2*>(wr + 4);
            ulonglong2 wq2 = *reinterpret_cast<const ulonglong2*>(wr + 8);
            ulonglong2 wq3 = *reinterpret_cast<const ulonglong2*>(wr + 12);

            fma2(acc[0][0], xv0, wq0.x); fma2(acc[0][1], xv0, wq0.y);
            fma2(acc[0][2], xv0, wq1.x); fma2(acc[0][3], xv0, wq1.y);
            fma2(acc[0][4], xv0, wq2.x); fma2(acc[0][5], xv0, wq2.y);
            fma2(acc[0][6], xv0, wq3.x); fma2(acc[0][7], xv0, wq3.y);
            fma2(acc[1][0], xv1, wq0.x); fma2(acc[1][1], xv1, wq0.y);
            fma2(acc[1][2], xv1, wq1.x); fma2(acc[1][3], xv1, wq1.y);
            fma2(acc[1][4], xv1, wq2.x); fma2(acc[1][5], xv1, wq2.y);
            fma2(acc[1][6], xv1, wq3.x); fma2(acc[1][7], xv1, wq3.y);
            fma2(acc[2][0], xv2, wq0.x); fma2(acc[2][1], xv2, wq0.y);
            fma2(acc[2][2], xv2, wq1.x); fma2(acc[2][3], xv2, wq1.y);
            fma2(acc[2][4], xv2, wq2.x); fma2(acc[2][5], xv2, wq2.y);
            fma2(acc[2][6], xv2, wq3.x); fma2(acc[2][7], xv2, wq3.y);
            fma2(acc[3][0], xv3, wq0.x); fma2(acc[3][1], xv3, wq0.y);
            fma2(acc[3][2], xv3, wq1.x); fma2(acc[3][3], xv3, wq1.y);
            fma2(acc[3][4], xv3, wq2.x); fma2(acc[3][5], xv3, wq2.y);
            fma2(acc[3][6], xv3, wq3.x); fma2(acc[3][7], xv3, wq3.y);
        }
        __syncthreads();
    }

    // ---- epilogue: direct float2 stores (u-pair); L2 merges 4 pairs -> full sector
    //      (validated in R5: measured HBM traffic == ideal with this pattern) ----
    float* yb = y + (size_t)b * COUT * TLEN * FF + (size_t)g * UU + u0;
#pragma unroll
    for (int k = 0; k < 4; ++k) {
        const int t = t0 + k * 32 + lane;
#pragma unroll
        for (int oo = 0; oo < 8; ++oo) {
            const int o  = og * 8 + oo;
            const int og_abs = oh * O_PER_CTA + o;
            float2 bb = *reinterpret_cast<const float2*>(bs + o * 8 + u0);
            float2 a  = unpack2(acc[k][oo]);
            float2 r  = make_float2(a.x + bb.x, a.y + bb.y);
            *reinterpret_cast<float2*>(yb + ((size_t)og_abs * TLEN + t) * FF) = r;
        }
    }
}

extern "C" void kernel_launch(void* const* d_in, const int* in_sizes, int n_in,
                              void* d_out, int out_size) {
    (void)in_sizes; (void)n_in; (void)out_size;
    const float* x    = (const float*)d_in[0];
    const float* w    = (const float*)d_in[1];
    const float* bias = (const float*)d_in[2];
    float*       y    = (float*)d_out;

    cudaFuncSetAttribute(grouped_linear_cf_kernel,
                         cudaFuncAttributeMaxDynamicSharedMemorySize, SMEM_BYTES);

    dim3 grid(GG, BQ, 16);   // 32 g x 8 b x (2 o-halves * 8 t-ranges) = 4096 CTAs
    grouped_linear_cf_kernel<<<grid, 512, SMEM_BYTES>>>(x, w, bias, y);
}

// round 15
// speedup vs baseline: 4.0130x; 4.0130x over previous
#include <cuda_runtime.h>
#include <cstdint>
#include <cstddef>

// Problem constants
#define BQ    8
#define CIN   64
#define TLEN  1024
#define FF    256
#define COUT  64
#define GG    32
#define UU    8

// Tiling: 1 CTA = 1024 threads = 32 warps = (4 u-pairs) x (8 o-octets)
// covers all 64 o, all 8 u, TILE_T = 64 t. No x re-reads.
#define TILE_T  64
#define ICHUNK  16
#define NCHUNK  (CIN / ICHUNK)        // 4

// SMEM (floats unless noted)
#define WS_FLOATS   (UU * CIN * 64)   // ws[up][i][o*2+j] : 4*64*128 = 32768 (128KB)
#define XS_UPSTRIDE 72                 // ull units (64 t + 8 pad)
#define XS_ILSTRIDE (4 * XS_UPSTRIDE)  // 288 ull
#define XS_STAGE    (ICHUNK * XS_ILSTRIDE)  // 4608 ull
#define XS_ULLS     (2 * XS_STAGE)     // 9216 ull = 18432 floats
#define YS_TSTRIDE  10                 // epilogue stage [o][t][u], 8+2 pad
#define YS_OSTRIDE  (TILE_T * YS_TSTRIDE)   // 640
#define YS_FLOATS   (32 * YS_OSTRIDE)  // 20480 (one 32-o pass)
#define XREGION_FL  (YS_FLOATS > 2*XS_STAGE*2 ? YS_FLOATS : 2*XS_STAGE*2)  // 20480
#define BS_FLOATS   512                // bias [64o][8u]
#define SMEM_BYTES  ((WS_FLOATS + XREGION_FL + BS_FLOATS) * 4)  // 215040 B

typedef unsigned long long ull;

__device__ __forceinline__ void fma2(ull& d, ull a, ull b) {
    asm("fma.rn.f32x2 %0, %1, %2, %0;" : "+l"(d) : "l"(a), "l"(b));
}
__device__ __forceinline__ float2 unpack2(ull v) {
    unsigned lo, hi;
    asm("mov.b64 {%0, %1}, %2;" : "=r"(lo), "=r"(hi) : "l"(v));
    return make_float2(__uint_as_float(lo), __uint_as_float(hi));
}
__device__ __forceinline__ void cp_async8(uint32_t dst, const void* src) {
    asm volatile("cp.async.ca.shared.global [%0], [%1], 8;\n" :: "r"(dst), "l"(src));
}
__device__ __forceinline__ void cp_commit() {
    asm volatile("cp.async.commit_group;\n" ::: "memory");
}
template <int N>
__device__ __forceinline__ void cp_wait() {
    asm volatile("cp.async.wait_group %0;\n" :: "n"(N) : "memory");
}

__global__ void __launch_bounds__(1024, 1)
grouped_linear_cf_kernel(const float* __restrict__ x,
                         const float* __restrict__ w,
                         const float* __restrict__ bias,
                         float* __restrict__ y)
{
    extern __shared__ float smem[];
    float* ws = smem;                                  // weights, 32768 fl
    ull*   xs = (ull*)(smem + WS_FLOATS);              // x stages (ull SoA)
    float* ys = (float*)xs;                            // epilogue stage overlay
    float* bs = smem + WS_FLOATS + XREGION_FL;         // bias slice

    const int g   = blockIdx.x;
    const int b   = blockIdx.y;
    const int tz  = blockIdx.z;            // 16 t-ranges of 64
    const int tid = threadIdx.x;

    const int lane = tid & 31;
    const int warp = tid >> 5;
    const int up   = warp & 3;             // u-pair 0..3
    const int og   = warp >> 3 == 0 ? (warp >> 2) : (warp >> 2);  // o-octet 0..7
    const int u0   = up * 2;
    const int t0   = tz * TILE_T;

    const float* xg = x + (size_t)b * CIN * TLEN * FF + (size_t)g * UU;

    // ---- chunk 0 cp.async: 16i x 4up x 64t = 4096 x 8B ----
    {
#pragma unroll
        for (int k = 0; k < 4; ++k) {
            int idx = tid + k * 1024;
            int upx = idx & 3;
            int t   = (idx >> 2) & 63;
            int il  = idx >> 8;
            const float* src = xg + (size_t)il * (TLEN * FF)
                                  + (size_t)(t0 + t) * FF + upx * 2;
            uint32_t dst = (uint32_t)__cvta_generic_to_shared(
                xs + il * XS_ILSTRIDE + upx * XS_UPSTRIDE + t);
            cp_async8(dst, src);
        }
        cp_commit();
    }

    // ---- full weight tile -> SMEM: ws[up][i][o*2+j] = w[g][2up+j][i][o] ----
    {
        const float* wgl = w + (size_t)g * (UU * CIN * COUT);
#pragma unroll
        for (int k = 0; k < 32; ++k) {
            int idx = tid + k * 1024;      // [u 8][i 64][o 64]
            int uu  = idx >> 12;
            int i   = (idx >> 6) & 63;
            int o   = idx & 63;
            ws[(uu >> 1) * (CIN * 128) + i * 128 + o * 2 + (uu & 1)] = wgl[idx];
        }
    }
    // ---- bias slice: bs[o*8+u] ----
    if (tid < 512)
        bs[tid] = bias[(size_t)(tid >> 3) * FF + g * UU + (tid & 7)];

    ull acc[2][8];
#pragma unroll
    for (int tt = 0; tt < 2; ++tt)
#pragma unroll
        for (int oo = 0; oo < 8; ++oo) acc[tt][oo] = 0ull;

    for (int ic = 0; ic < NCHUNK; ++ic) {
        if (ic + 1 < NCHUNK) {
            ull* dstb = xs + ((ic + 1) & 1) * XS_STAGE;
            const int ibase = (ic + 1) * ICHUNK;
#pragma unroll
            for (int k = 0; k < 4; ++k) {
                int idx = tid + k * 1024;
                int upx = idx & 3;
                int t   = (idx >> 2) & 63;
                int il  = idx >> 8;
                const float* src = xg + (size_t)(ibase + il) * (TLEN * FF)
                                      + (size_t)(t0 + t) * FF + upx * 2;
                uint32_t dst = (uint32_t)__cvta_generic_to_shared(
                    dstb + il * XS_ILSTRIDE + upx * XS_UPSTRIDE + t);
                cp_async8(dst, src);
            }
            cp_commit();
            cp_wait<1>();
        } else {
            cp_wait<0>();
        }
        __syncthreads();

        const ull*   xb = xs + (ic & 1) * XS_STAGE + up * XS_UPSTRIDE + lane;
        const float* wb = ws + up * (CIN * 128) + og * 16 + ic * ICHUNK * 128;

#pragma unroll
        for (int il = 0; il < ICHUNK; ++il) {
            // x u-pairs at t = lane, lane+32 (coalesced LDS.64)
            ull xv0 = xb[il * XS_ILSTRIDE];
            ull xv1 = xb[il * XS_ILSTRIDE + 32];

            const float* wr = wb + il * 128;
            // first 4 o-pairs (limits live wq regs to 8)
            ulonglong2 wq0 = *reinterpret_cast<const ulonglong2*>(wr);
            ulonglong2 wq1 = *reinterpret_cast<const ulonglong2*>(wr + 4);
            fma2(acc[0][0], xv0, wq0.x); fma2(acc[0][1], xv0, wq0.y);
            fma2(acc[0][2], xv0, wq1.x); fma2(acc[0][3], xv0, wq1.y);
            fma2(acc[1][0], xv1, wq0.x); fma2(acc[1][1], xv1, wq0.y);
            fma2(acc[1][2], xv1, wq1.x); fma2(acc[1][3], xv1, wq1.y);
            // last 4 o-pairs
            ulonglong2 wq2 = *reinterpret_cast<const ulonglong2*>(wr + 8);
            ulonglong2 wq3 = *reinterpret_cast<const ulonglong2*>(wr + 12);
            fma2(acc[0][4], xv0, wq2.x); fma2(acc[0][5], xv0, wq2.y);
            fma2(acc[0][6], xv0, wq3.x); fma2(acc[0][7], xv0, wq3.y);
            fma2(acc[1][4], xv1, wq2.x); fma2(acc[1][5], xv1, wq2.y);
            fma2(acc[1][6], xv1, wq3.x); fma2(acc[1][7], xv1, wq3.y);
        }
        __syncthreads();
    }

    // ---- staged epilogue: 2 passes over 32-o halves through smem ----
    float* yb = y + (size_t)b * COUT * TLEN * FF + (size_t)g * UU;
#pragma unroll
    for (int p = 0; p < 2; ++p) {
        if (p) __syncthreads();    // previous pass's reads done before overwrite
        if ((og >> 2) == p) {
            const int obase = (og & 3) * 8;
#pragma unroll
            for (int tt = 0; tt < 2; ++tt) {
                const int t = lane + tt * 32;
#pragma unroll
                for (int oo = 0; oo < 8; ++oo)
                    *reinterpret_cast<float2*>(
                        ys + (obase + oo) * YS_OSTRIDE + t * YS_TSTRIDE + u0) =
                        unpack2(acc[tt][oo]);
            }
        }
        __syncthreads();

        // cooperative read: each thread 2 (o,t) cells -> 2 STG.128 each
#pragma unroll
        for (int k = 0; k < 2; ++k) {
            int idx = tid + k * 1024;      // [o 32][t 64]
            int o   = idx >> 6;
            int t   = idx & 63;
            const float* r = ys + o * YS_OSTRIDE + t * YS_TSTRIDE;
            float2 v0 = *reinterpret_cast<const float2*>(r);
            float2 v1 = *reinterpret_cast<const float2*>(r + 2);
            float2 v2 = *reinterpret_cast<const float2*>(r + 4);
            float2 v3 = *reinterpret_cast<const float2*>(r + 6);
            const int oabs = p * 32 + o;
            float4 b0 = *reinterpret_cast<const float4*>(bs + oabs * 8);
            float4 b1 = *reinterpret_cast<const float4*>(bs + oabs * 8 + 4);
            float4 r0 = make_float4(v0.x + b0.x, v0.y + b0.y, v1.x + b0.z, v1.y + b0.w);
            float4 r1 = make_float4(v2.x + b1.x, v2.y + b1.y, v3.x + b1.z, v3.y + b1.w);
            float* dst = yb + ((size_t)oabs * TLEN + t0 + t) * FF;
            *reinterpret_cast<float4*>(dst)     = r0;
            *reinterpret_cast<float4*>(dst + 4) = r1;
        }
    }
}

extern "C" void kernel_launch(void* const* d_in, const int* in_sizes, int n_in,
                              void* d_out, int out_size) {
    (void)in_sizes; (void)n_in; (void)out_size;
    const float* x    = (const float*)d_in[0];
    const float* w    = (const float*)d_in[1];
    const float* bias = (const float*)d_in[2];
    float*       y    = (float*)d_out;

    cudaFuncSetAttribute(grouped_linear_cf_kernel,
                         cudaFuncAttributeMaxDynamicSharedMemorySize, SMEM_BYTES);

    dim3 grid(GG, BQ, 16);   // 32 g x 8 b x 16 t-ranges = 4096 CTAs (1 per SM wave)
    grouped_linear_cf_kernel<<<grid, 1024, SMEM_BYTES>>>(x, w, bias, y);
}

// round 17
// speedup vs baseline: 5.4598x; 1.3605x over previous
#include <cuda_runtime.h>
#include <cstdint>
#include <cstddef>

// Problem constants
#define BQ    8
#define CIN   64
#define TLEN  1024
#define FF    256
#define COUT  64
#define GG    32
#define UU    8

// Tiling: 512 threads = 16 warps = (8 u) x (2 o-halves); lanes = (4 og) x (8 tg)
// Thread tile: 1 u, 4 o-pairs (8 o), 8 t  -> acc 32 ull = 64 regs
#define TILE_T  64
#define ICHUNK  8
#define NCHUNK  (CIN / ICHUNK)      // 8

// SMEM (floats)
#define WS_FL       32768            // ws[u][i][o] = w[g] verbatim (128KB)
#define XS_TSTRIDE  12               // 8 u + 4 pad  (16B-aligned rows, conflict-free)
#define XS_ILSTRIDE (TILE_T * XS_TSTRIDE)   // 768
#define XS_CHUNK    (ICHUNK * XS_ILSTRIDE)  // 6144
#define XS_FL       (2 * XS_CHUNK)          // 12288
#define BS_OFF      (WS_FL + XS_FL)         // 45056
#define SMEM_FL     (BS_OFF + 512)
#define SMEM_BYTES  (SMEM_FL * 4)           // 182272

// Epilogue transpose overlay (over dead ws+xs): ys[u][o][t], o-stride 65 (== 1 mod 32)
#define YS_OSTRIDE  65
#define YS_USTRIDE  (64 * YS_OSTRIDE)       // 4160; 8*4160 = 33280 < 45056 ok

typedef unsigned long long ull;

__device__ __forceinline__ ull splat2(float x) {
    ull d; unsigned u = __float_as_uint(x);
    asm("mov.b64 %0, {%1, %1};" : "=l"(d) : "r"(u));
    return d;
}
__device__ __forceinline__ void fma2(ull& d, ull a, ull b) {
    asm("fma.rn.f32x2 %0, %1, %2, %0;" : "+l"(d) : "l"(a), "l"(b));
}
__device__ __forceinline__ float2 unpack2(ull v) {
    unsigned lo, hi;
    asm("mov.b64 {%0, %1}, %2;" : "=r"(lo), "=r"(hi) : "l"(v));
    return make_float2(__uint_as_float(lo), __uint_as_float(hi));
}
__device__ __forceinline__ void cp_async16(uint32_t dst, const void* src) {
    asm volatile("cp.async.cg.shared.global [%0], [%1], 16;\n" :: "r"(dst), "l"(src));
}
__device__ __forceinline__ void cp_commit() {
    asm volatile("cp.async.commit_group;\n" ::: "memory");
}
template <int N>
__device__ __forceinline__ void cp_wait() {
    asm volatile("cp.async.wait_group %0;\n" :: "n"(N) : "memory");
}

__global__ void __launch_bounds__(512, 1)
grouped_linear_cf_kernel(const float* __restrict__ x,
                         const float* __restrict__ w,
                         const float* __restrict__ bias,
                         float* __restrict__ y)
{
    extern __shared__ float smem[];
    float* ws = smem;                 // [u][i][o]
    float* xs = smem + WS_FL;         // [stage][il][t(stride12) -> 8u]
    float* bs = smem + BS_OFF;        // bias [o][u]
    float* ys = smem;                 // epilogue overlay [u][o(65)][t]
    uint32_t xs_s = (uint32_t)__cvta_generic_to_shared(xs);

    const int g   = blockIdx.x;
    const int b   = blockIdx.y;
    const int tz  = blockIdx.z;           // 16 t-ranges of 64
    const int tid = threadIdx.x;

    const int lane = tid & 31;
    const int warp = tid >> 5;
    const int u    = warp >> 1;           // 0..7
    const int oh   = warp & 1;            // o-half
    const int og   = lane >> 3;           // 0..3
    const int tg   = lane & 7;            // 0..7
    const int ob   = oh * 32 + og * 8;    // thread o-base (8 o's)
    const int t0   = tz * TILE_T;

    const float* xg = x + (size_t)b * CIN * TLEN * FF + (size_t)g * UU;

    // ---- prologue: chunk 0 via cp.async16 (1024 = 8il x 64t x 2 halves) ----
    {
#pragma unroll
        for (int k = 0; k < 2; ++k) {
            int idx = tid + k * 512;
            int uh  = idx & 1;
            int t   = (idx >> 1) & 63;
            int il  = idx >> 7;
            const float* src = xg + (size_t)il * (TLEN * FF) + (size_t)(t0 + t) * FF + uh * 4;
            uint32_t dst = xs_s + (uint32_t)(il * XS_ILSTRIDE + t * XS_TSTRIDE + uh * 4) * 4;
            cp_async16(dst, src);
        }
        cp_commit();
    }

    // ---- weights -> SMEM verbatim ([u][i][o] is w[g]'s native layout) ----
    {
        const float4* wg = reinterpret_cast<const float4*>(w + (size_t)g * (UU * CIN * COUT));
#pragma unroll
        for (int k = 0; k < 16; ++k)
            reinterpret_cast<float4*>(ws)[tid + k * 512] = wg[tid + k * 512];
    }
    if (tid < 512)
        bs[tid] = bias[(size_t)(tid >> 3) * FF + g * UU + (tid & 7)];

    ull acc[8][4];
#pragma unroll
    for (int j = 0; j < 8; ++j)
#pragma unroll
        for (int p = 0; p < 4; ++p) acc[j][p] = 0ull;

    for (int ic = 0; ic < NCHUNK; ++ic) {
        if (ic + 1 < NCHUNK) {
            const int ibase = (ic + 1) * ICHUNK;
            uint32_t dstb = xs_s + (uint32_t)(((ic + 1) & 1) * XS_CHUNK) * 4;
#pragma unroll
            for (int k = 0; k < 2; ++k) {
                int idx = tid + k * 512;
                int uh  = idx & 1;
                int t   = (idx >> 1) & 63;
                int il  = idx >> 7;
                const float* src = xg + (size_t)(ibase + il) * (TLEN * FF)
                                      + (size_t)(t0 + t) * FF + uh * 4;
                uint32_t dst = dstb + (uint32_t)(il * XS_ILSTRIDE + t * XS_TSTRIDE + uh * 4) * 4;
                cp_async16(dst, src);
            }
            cp_commit();
            cp_wait<1>();
        } else {
            cp_wait<0>();
        }
        __syncthreads();

        // x: scalar reads at [il][t=j*8+tg][u]  (8 distinct banks, 4-lane bcast -> 1 wf)
        const float* xb = xs + (ic & 1) * XS_CHUNK + tg * XS_TSTRIDE + u;
        // w: 8 consecutive o's (32B) at [u][i][ob]  (4 bank-groups -> 4-wf floor)
        const float* wb = ws + u * (CIN * COUT) + ic * ICHUNK * COUT + ob;

#pragma unroll
        for (int il = 0; il < ICHUNK; ++il) {
            const float* wr = wb + il * COUT;
            ulonglong2 w0 = *reinterpret_cast<const ulonglong2*>(wr);      // o-pairs 0,1
            ulonglong2 w1 = *reinterpret_cast<const ulonglong2*>(wr + 4);  // o-pairs 2,3
            const float* xr = xb + il * XS_ILSTRIDE;
#pragma unroll
            for (int j = 0; j < 8; ++j) {
                ull s = splat2(xr[j * 8 * XS_TSTRIDE]);
                fma2(acc[j][0], s, w0.x);
                fma2(acc[j][1], s, w0.y);
                fma2(acc[j][2], s, w1.x);
                fma2(acc[j][3], s, w1.y);
            }
        }
        __syncthreads();
    }

    // ---- epilogue: transpose via smem overlay (ws/xs dead) ----
    // STS: addr = u*4160 + o*65 + t ; bank = (o + 8j + tg) mod 32 -> conflict-free
#pragma unroll
    for (int j = 0; j < 8; ++j) {
        const int t = j * 8 + tg;
#pragma unroll
        for (int p = 0; p < 4; ++p) {
            float2 v = unpack2(acc[j][p]);
            const int o = ob + 2 * p;
            ys[u * YS_USTRIDE + o * YS_OSTRIDE + t]       = v.x;
            ys[u * YS_USTRIDE + (o + 1) * YS_OSTRIDE + t] = v.y;
        }
    }
    __syncthreads();

    // gather 8 u's per (o,t) -> one full 32B sector store
    float* yb = y + (size_t)b * COUT * TLEN * FF + (size_t)g * UU;
#pragma unroll
    for (int k = 0; k < 8; ++k) {
        int sidx = tid + k * 512;          // [o 64][t 64]
        int o    = sidx >> 6;
        int t    = sidx & 63;
        float v[8];
#pragma unroll
        for (int uu = 0; uu < 8; ++uu)
            v[uu] = ys[uu * YS_USTRIDE + o * YS_OSTRIDE + t];
        float4 b0 = *reinterpret_cast<const float4*>(bs + o * 8);
        float4 b1 = *reinterpret_cast<const float4*>(bs + o * 8 + 4);
        float4 r0 = make_float4(v[0] + b0.x, v[1] + b0.y, v[2] + b0.z, v[3] + b0.w);
        float4 r1 = make_float4(v[4] + b1.x, v[5] + b1.y, v[6] + b1.z, v[7] + b1.w);
        float* dst = yb + ((size_t)o * TLEN + t0 + t) * FF;
        *reinterpret_cast<float4*>(dst)     = r0;
        *reinterpret_cast<float4*>(dst + 4) = r1;
    }
}

extern "C" void kernel_launch(void* const* d_in, const int* in_sizes, int n_in,
                              void* d_out, int out_size) {
    (void)in_sizes; (void)n_in; (void)out_size;
    const float* x    = (const float*)d_in[0];
    const float* w    = (const float*)d_in[1];
    const float* bias = (const float*)d_in[2];
    float*       y    = (float*)d_out;

    cudaFuncSetAttribute(grouped_linear_cf_kernel,
                         cudaFuncAttributeMaxDynamicSharedMemorySize, SMEM_BYTES);

    dim3 grid(GG, BQ, 16);   // 32 g x 8 b x 16 t-ranges = 4096 CTAs
    grouped_linear_cf_kernel<<<grid, 512, SMEM_BYTES>>>(x, w, bias, y);
}